// round 17
// baseline (speedup 1.0000x reference)
#include <cuda_runtime.h>

// MaxUnpool2D: B=8, H=W=128, C=64, KH=KW=2, HOUT=WOUT=256.
// Mask guarantees each input element's target lies inside its own disjoint 2x2
// output window => unique targets (plain stores), windows tile the output
// exactly (no zero-fill pass).
//
// Round 17: DRAM bus-turnaround test. All cache-policy cells are measured or
// unreachable; all passing kernels pin at 5.69 TB/s with a 2:1 w:r mix that
// interleaves reads/writes at ~128B granularity. This kernel front-batches:
// each thread owns 4 elements, issues all 8 loads back-to-back (4KB/warp read
// burst), then all 16 stores back-to-back (8KB/warp write burst) — longer
// same-direction runs at the DRAM controllers, fewer turnarounds.

#define B_    8
#define H_    128
#define W_    128
#define C_    64
#define HOUT_ 256
#define WOUT_ 256
#define C4_   16                          // float4 groups per pixel
#define N4_   (B_ * H_ * W_ * C4_)        // 2,097,152 float4 elements
#define GRID_ 2048
#define BLK_  256
#define STRIDE_ (GRID_ * BLK_)            // 524,288
#define ITER_  (N4_ / STRIDE_)            // 4

__global__ void __launch_bounds__(BLK_)
max_unpool_kernel(const float4* __restrict__ x4,
                  const int4*   __restrict__ m4,
                  float4*       __restrict__ out4)
{
    const int t0 = blockIdx.x * BLK_ + threadIdx.x;

    // ---- Phase 1: front-batch ALL loads (8 independent LDG.128) ----
    float4 v[ITER_];
    int4   m[ITER_];
#pragma unroll
    for (int i = 0; i < ITER_; ++i) {
        v[i] = x4[t0 + i * STRIDE_];
        m[i] = m4[t0 + i * STRIDE_];
    }

    // ---- Phase 2: compute + batch ALL stores (16 STG.128) ----
#pragma unroll
    for (int i = 0; i < ITER_; ++i) {
        const int t = t0 + i * STRIDE_;

        // t layout: (((b*H + h)*W + w) * C4 + c4)
        const int c4 = t & (C4_ - 1);
        const int w  = (t >> 4) & (W_ - 1);
        const int h  = (t >> 11) & (H_ - 1);
        const int b  = t >> 18;

        const int p00   = (h * 2 * WOUT_ + w * 2) * C_ + c4 * 4;
        const int base4 = b * (HOUT_ * WOUT_ * C4_) + (p00 >> 2);

        const float vx[4] = {v[i].x, v[i].y, v[i].z, v[i].w};
        const int   mi[4] = {m[i].x, m[i].y, m[i].z, m[i].w};

#pragma unroll
        for (int dh = 0; dh < 2; ++dh) {
#pragma unroll
            for (int dw = 0; dw < 2; ++dw) {
                const int p = p00 + dh * (WOUT_ * C_) + dw * C_;
                float4 o;
                o.x = (mi[0] == p + 0) ? vx[0] : 0.0f;
                o.y = (mi[1] == p + 1) ? vx[1] : 0.0f;
                o.z = (mi[2] == p + 2) ? vx[2] : 0.0f;
                o.w = (mi[3] == p + 3) ? vx[3] : 0.0f;
                out4[base4 + dh * (WOUT_ * C4_) + dw * C4_] = o;
            }
        }
    }
}

extern "C" void kernel_launch(void* const* d_in, const int* in_sizes, int n_in,
                              void* d_out, int out_size)
{
    const float4* x4 = (const float4*)d_in[0];  // input_pool f32 [8,128,128,64]
    const int4*   m4 = (const int4*)d_in[1];    // pool_mask  i32 [8,128,128,64]
    float4* out4 = (float4*)d_out;              // [8,256,256,64] f32

    max_unpool_kernel<<<GRID_, BLK_>>>(x4, m4, out4);
}